// round 14
// baseline (speedup 1.0000x reference)
#include <cuda_runtime.h>
#include <math.h>

#define BB 16
#define QQ 2304
#define CC 1204
#define NPB (QQ*CC)          /* 2774016 elements per batch */
#define NF4 (NPB/4)          /* 693504 float4 per batch */
#define KTOP 100
#define CAP 4096             /* per-batch candidate store (u64 keys) */
#define GPB 740              /* blocks per batch: 16*740 = 11840 = 10 waves of 1184 */
#define TIECAP 512           /* value-tie list cap; beyond -> exact fallback */
#define TAUL 3.49f           /* fixed logit threshold; E[cnt]~668/batch.
                                Correctness does NOT depend on it: the select
                                phase falls back to a full exact rescan
                                whenever cnt out of range or ties overflow. */

__device__ unsigned           g_cnt[BB];        /* zero-init; reset by selector */
__device__ unsigned           g_done[BB];       /* zero-init; reset by selector */
__device__ unsigned           g_h0[BB][2048];   /* pass-0 hist; reset by selector */
__device__ unsigned long long g_key[BB][CAP];

__device__ __forceinline__ float fsig_acc(float x){ return 1.0f/(1.0f+expf(-x)); }

// ---------------------------------------------------------------------------
// Fused kernel, 11840 blocks of 256 threads (exactly 10 waves @ 8 blocks/SM).
// Phase 1: stream-filter one batch slice — 4x LDG.128 + fmax tree + 1 compare
// per 16 elements. Rare hits (~670/batch) compute the EXACT value (accurate
// expf, obj multiply on last channel), push
//   key = (float_bits(value) << 32) | ~local_idx
// (descending u64 order == jax.lax.top_k order: value desc, index asc),
// and bump the per-batch 2048-bin pass-0 histogram (bits[21:32) of value).
// Phase 2 (last block per batch via threadfence+ticket): radix select where
// pass 0 comes straight from the prebuilt histogram (no key scan), passes 1-2
// scan the L2-hot keys, exact index tie-break, rank sort, box epilogue.
// Selector smem ~11KB so streaming blocks keep their L1D carveout.
// ---------------------------------------------------------------------------
__global__ __launch_bounds__(256, 8)
void k_fused(const float* __restrict__ logits,
             const float* __restrict__ obj,
             const float* __restrict__ boxes,
             const int*   __restrict__ tsraw,
             float* __restrict__ dout)
{
    unsigned blk = blockIdx.x;
    unsigned b   = blk / (unsigned)GPB;
    unsigned sl  = blk - b*(unsigned)GPB;
    int tid = threadIdx.x;

    const float4* L4 = (const float4*)(logits + (size_t)b*NPB);
    const float*  L  = logits + (size_t)b*NPB;
    const float*  O  = obj    + (size_t)b*QQ;

    // ---------------- Phase 1: filter this block's slice ------------------
    {
        unsigned base = sl*256u + (unsigned)tid;
        const unsigned stride = (unsigned)GPB*256u;
        unsigned ii[4]; bool act[4]; float4 v[4];
        #pragma unroll
        for (int j=0;j<4;j++){
            unsigned i = base + (unsigned)j*stride;
            act[j] = (i < (unsigned)NF4);
            ii[j]  = act[j] ? i : 0u;
        }
        #pragma unroll
        for (int j=0;j<4;j++) if (act[j]) v[j] = __ldg(&L4[ii[j]]);

        #pragma unroll
        for (int j=0;j<4;j++){
            if (!act[j]) continue;
            float m = fmaxf(fmaxf(v[j].x, v[j].y), fmaxf(v[j].z, v[j].w));
            if (m >= TAUL){
                float fs[4] = {v[j].x, v[j].y, v[j].z, v[j].w};
                #pragma unroll
                for (int t=0;t<4;t++){
                    if (fs[t] >= TAUL){
                        unsigned e = ii[j]*4u + (unsigned)t;
                        unsigned q = e/(unsigned)CC;
                        unsigned c = e - q*(unsigned)CC;
                        float val = fsig_acc(fs[t]);
                        if (c == (unsigned)(CC-1)) val *= __ldg(&O[q]);
                        unsigned vb = __float_as_uint(val);
                        unsigned long long key =
                            ((unsigned long long)vb << 32) | (unsigned)(~e);
                        atomicAdd(&g_h0[b][(vb>>21)&2047u], 1u);
                        unsigned p = atomicAdd(&g_cnt[b], 1u);
                        if (p < (unsigned)CAP) g_key[b][p] = key;
                    }
                }
            }
        }
    }

    // ---------------- ticket: last block of batch b becomes selector ------
    __shared__ unsigned sTicket;
    __syncthreads();
    if (tid==0){
        __threadfence();
        sTicket = atomicAdd(&g_done[b], 1u);
    }
    __syncthreads();
    if (sTicket != (unsigned)(GPB-1)) return;

    // ---------------- Phase 2: per-batch select + epilogue ----------------
    __shared__ unsigned           hist[2048];     // 8 KB
    __shared__ unsigned long long tl[TIECAP];     // 4 KB (value ties)
    __shared__ unsigned long long outk[KTOP];     // 800 B
    __shared__ unsigned           wsum[8];
    __shared__ unsigned long long wmax[8];
    __shared__ unsigned           sPref, sRemain, sNc, sTc, sCnt, sTie;
    __shared__ unsigned long long sPrev;

    // early: issue target_sizes loads so DRAM latency overlaps the barriers
    int tsOdd = 0;                // OR of odd words -> int64 iff all zero
    #pragma unroll
    for (int i2=1; i2<32; i2+=2) tsOdd |= tsraw[i2];
    int w0 = tsraw[4*b+0], w1 = tsraw[4*b+1], w2 = tsraw[4*b+2], w3 = tsraw[4*b+3];

    if (tid==0){
        sCnt = g_cnt[b];
        g_cnt[b]  = 0u;     // replay invariants
        g_done[b] = 0u;
        sPref = 0u; sRemain = KTOP; sNc = 0u; sTc = 0u; sTie = 0u;
    }
    __syncthreads();
    unsigned cnt = sCnt;
    bool bad = (cnt < (unsigned)KTOP) || (cnt > (unsigned)CAP);
    int lane = tid & 31, wid = tid >> 5;
    const unsigned long long* GK = g_key[b];

    if (!bad){
        int n = (int)cnt;

        // ---- 3-pass radix select on the 32-bit value (11/11/10 bits) -----
        // pass 0 histogram comes from g_h0 (built during the filter).
        const int shf[3]  = {21, 10, 0};
        const int bits[3] = {11, 11, 10};
        #pragma unroll
        for (int p=0; p<3; p++){
            unsigned rem  = sRemain;
            unsigned pref = sPref;
            int shift = shf[p], nb = bits[p];
            if (p==0){
                #pragma unroll
                for (int j=0;j<8;j++){
                    unsigned bin = (unsigned)tid + 256u*j;
                    hist[bin] = g_h0[b][bin];
                    g_h0[b][bin] = 0u;          // reset for next replay
                }
            } else {
                #pragma unroll
                for (int j=0;j<8;j++) hist[tid + 256*j] = 0u;
            }
            __syncthreads();
            if (p>0){
                for (int i=tid; i<n; i+=256){
                    unsigned v = (unsigned)(__ldg(&GK[i]) >> 32);
                    if ((v >> (shift+nb)) == pref)
                        atomicAdd(&hist[(v>>shift) & ((1u<<nb)-1u)], 1u);
                }
                __syncthreads();
            }
            // descending scan: thread t covers bins [2047-8t .. 2040-8t]
            int base = 2047 - tid*8;
            unsigned h[8]; unsigned sum = 0;
            #pragma unroll
            for (int j=0;j<8;j++){ h[j] = hist[base-j]; sum += h[j]; }
            unsigned inc = sum;
            #pragma unroll
            for (int off=1; off<32; off<<=1){
                unsigned o = __shfl_up_sync(0xFFFFFFFFu, inc, off);
                if (lane>=off) inc += o;
            }
            if (lane==31) wsum[wid] = inc;
            __syncthreads();
            unsigned wbase = 0;
            for (int w=0; w<wid; w++) wbase += wsum[w];
            unsigned excl = wbase + (inc - sum);
            if (excl < rem && rem <= excl + sum){
                unsigned r = rem - excl;
                unsigned c = 0;
                #pragma unroll
                for (int j=0;j<8;j++){
                    if (c + h[j] >= r){
                        sPref   = (pref << nb) | (unsigned)(base - j);
                        sRemain = r - c;
                        if (p==2) sTie = h[j];
                        break;
                    }
                    c += h[j];
                }
            }
            __syncthreads();
        }
        unsigned V   = sPref;       // exact 32-bit pivot value bits
        unsigned rem = sRemain;     // how many ties to take (by smallest idx)
        unsigned tc0 = sTie;        // exact tie count from histogram

        if (tc0 <= (unsigned)TIECAP){
            // collect: val > V -> outk (exactly KTOP-rem); val == V -> ties
            for (int i=tid; i<n; i+=256){
                unsigned long long kk = __ldg(&GK[i]);
                unsigned v = (unsigned)(kk >> 32);
                if (v > V){
                    outk[atomicAdd(&sNc,1u)] = kk;
                } else if (v == V){
                    unsigned p2 = atomicAdd(&sTc,1u);
                    if (p2 < (unsigned)TIECAP) tl[p2] = kk;
                }
            }
            __syncthreads();
            unsigned tc = sTc;
            // tie-break: take the rem ties with largest key (= smallest idx)
            for (unsigned j=tid; j<tc; j+=256u){
                unsigned long long kj = tl[j];
                unsigned c = 0;
                for (unsigned i=0;i<tc;i++) c += (tl[i] > kj) ? 1u : 0u;
                if (c < rem) outk[atomicAdd(&sNc,1u)] = kj;
            }
            __syncthreads();

            // rank sort of 100 unique keys
            unsigned long long myk = 0ull; int rank = 0;
            if (tid < KTOP){
                myk = outk[tid];
                for (int j=0;j<KTOP;j++) rank += (outk[j] > myk) ? 1 : 0;
            }
            __syncthreads();
            if (tid < KTOP) outk[rank] = myk;
            __syncthreads();
        } else {
            bad = true;   // absurd tie degeneracy -> exact fallback below
        }
    } else {
        // reset pass-0 histogram even on the fallback path (replay invariant)
        #pragma unroll
        for (int j=0;j<8;j++) g_h0[b][(unsigned)tid + 256u*j] = 0u;
    }

    if (bad){
        // Fully correct fallback: 100 bounded full-batch argmax passes.
        if (tid==0) sPrev = 0xFFFFFFFFFFFFFFFFull;
        __syncthreads();
        for (int k=0;k<KTOP;k++){
            unsigned long long prev = sPrev;
            unsigned long long bm = 0ull;
            for (unsigned i=tid; i<(unsigned)NPB; i+=256u){
                float lg = L[i];
                float v  = fsig_acc(lg);
                unsigned q = i/(unsigned)CC;
                unsigned c = i - q*(unsigned)CC;
                if (c == (unsigned)(CC-1)) v *= O[q];
                unsigned long long kk =
                    ((unsigned long long)__float_as_uint(v) << 32) | (unsigned)(~i);
                if (kk < prev && kk > bm) bm = kk;
            }
            #pragma unroll
            for (int off=16; off; off>>=1){
                unsigned long long om = __shfl_down_sync(0xFFFFFFFFu, bm, off);
                if (om > bm) bm = om;
            }
            if (lane==0) wmax[wid]=bm;
            __syncthreads();
            if (tid==0){
                unsigned long long best=0ull;
                for (int w=0;w<8;w++) if (wmax[w]>best) best=wmax[w];
                outk[k]=best; sPrev=best;
            }
            __syncthreads();
        }
    }

    // ---- target_sizes (loaded early): int64 iff all odd words zero -------
    bool is64 = (tsOdd == 0);
    long long t0, t1;
    if (is64){
        t0 = (long long)(unsigned)w0 | ((long long)w1 << 32);
        t1 = (long long)(unsigned)w2 | ((long long)w3 << 32);
    } else {
        t0 = (long long)tsraw[2*b]; t1 = (long long)tsraw[2*b+1];
    }
    float scale = (float)(t0 > t1 ? t0 : t1);
    float limW  = (float)t1;
    float limH  = (float)t0;
    const float4* BX = (const float4*)boxes + (size_t)b*QQ;

    for (int k=tid; k<KTOP; k+=256){
        unsigned long long kk = outk[k];
        float    score = __uint_as_float((unsigned)(kk>>32));
        unsigned idx   = ~((unsigned)(kk & 0xFFFFFFFFull));
        unsigned q   = idx/(unsigned)CC;
        unsigned lab = idx - q*(unsigned)CC;

        dout[b*KTOP + k]            = score;
        dout[BB*KTOP + b*KTOP + k]  = (float)lab;

        float4 bx = BX[q];
        float x0 = (bx.x - 0.5f*bx.z)*scale;
        float y0 = (bx.y - 0.5f*bx.w)*scale;
        float x1 = (bx.x + 0.5f*bx.z)*scale;
        float y1 = (bx.y + 0.5f*bx.w)*scale;
        x0 = fminf(fmaxf(x0,0.0f), limW);
        y0 = fminf(fmaxf(y0,0.0f), limH);
        x1 = fminf(fmaxf(x1,0.0f), limW);
        y1 = fminf(fmaxf(y1,0.0f), limH);
        float* ob = dout + 2*BB*KTOP + ((size_t)(b*KTOP + k))*4;
        ob[0]=x0; ob[1]=y0; ob[2]=x1; ob[3]=y1;
    }
}

// ---------------------------------------------------------------------------
extern "C" void kernel_launch(void* const* d_in, const int* in_sizes, int n_in,
                              void* d_out, int out_size)
{
    const float* logits = (const float*)d_in[0];
    const float* obj    = (const float*)d_in[1];
    const float* boxes  = (const float*)d_in[2];
    const int*   tsraw  = (const int*)  d_in[3];
    float* dout = (float*)d_out;

    k_fused<<<BB*GPB, 256>>>(logits, obj, boxes, tsraw, dout);   // 11840 blocks
}

// round 15
// speedup vs baseline: 1.1175x; 1.1175x over previous
#include <cuda_runtime.h>
#include <math.h>

#define BB 16
#define QQ 2304
#define CC 1204
#define NPB (QQ*CC)          /* 2774016 elements per batch */
#define NF4 (NPB/4)          /* 693504 float4 per batch */
#define KTOP 100
#define CAP 4096             /* per-batch candidate store (u64 keys) */
#define GPB 678              /* blocks per batch: 678*256*4 = 694272 >= NF4 */
#define KPT 7                /* selector keys per thread (registers) */
#define CAPS (256*KPT)       /* 1792: selector fast-path limit */
#define TIECAP 512           /* value-tie list cap; beyond -> exact fallback */
#define TAUL 3.49f           /* fixed logit threshold; E[cnt]~668/batch.
                                Correctness does NOT depend on it: the select
                                phase falls back to a full exact rescan
                                whenever cnt out of range or ties overflow. */

__device__ unsigned           g_cnt[BB];    /* zero-init; reset by selector */
__device__ unsigned           g_done[BB];   /* zero-init; reset by selector */
__device__ unsigned long long g_key[BB][CAP];

__device__ __forceinline__ float fsig_acc(float x){ return 1.0f/(1.0f+expf(-x)); }

// ---------------------------------------------------------------------------
// Fused kernel, 10848 blocks of 256 threads — stream phase byte-identical to
// the best measured configuration (round 11).
// Phase 1: stream-filter one batch slice — 4x LDG.128 + fmax tree + 1 compare
// per 16 elements. Rare hits (~670/batch) compute the EXACT value (accurate
// expf, obj multiply on last channel) and push
//   key = (float_bits(value) << 32) | ~local_idx
// (descending u64 order == jax.lax.top_k order: value desc, index asc).
// Phase 2 (last block per batch via threadfence+ticket): keys are loaded from
// L2 ONCE into per-thread registers, then a 3-pass radix select (11/11/10
// bits, 2048 bins) + collect + exact tie-break + rank sort run entirely from
// registers/shared — removing 3 of 4 L2 scan rounds from the exposed tail.
// ---------------------------------------------------------------------------
__global__ __launch_bounds__(256, 8)
void k_fused(const float* __restrict__ logits,
             const float* __restrict__ obj,
             const float* __restrict__ boxes,
             const int*   __restrict__ tsraw,
             float* __restrict__ dout)
{
    unsigned blk = blockIdx.x;
    unsigned b   = blk / (unsigned)GPB;
    unsigned sl  = blk - b*(unsigned)GPB;
    int tid = threadIdx.x;

    const float4* L4 = (const float4*)(logits + (size_t)b*NPB);
    const float*  L  = logits + (size_t)b*NPB;
    const float*  O  = obj    + (size_t)b*QQ;

    // ---------------- Phase 1: filter this block's slice ------------------
    {
        unsigned base = sl*256u + (unsigned)tid;
        const unsigned stride = (unsigned)GPB*256u;
        unsigned ii[4]; bool act[4]; float4 v[4];
        #pragma unroll
        for (int j=0;j<4;j++){
            unsigned i = base + (unsigned)j*stride;
            act[j] = (i < (unsigned)NF4);
            ii[j]  = act[j] ? i : 0u;
        }
        #pragma unroll
        for (int j=0;j<4;j++) if (act[j]) v[j] = __ldg(&L4[ii[j]]);

        #pragma unroll
        for (int j=0;j<4;j++){
            if (!act[j]) continue;
            float m = fmaxf(fmaxf(v[j].x, v[j].y), fmaxf(v[j].z, v[j].w));
            if (m >= TAUL){
                float fs[4] = {v[j].x, v[j].y, v[j].z, v[j].w};
                #pragma unroll
                for (int t=0;t<4;t++){
                    if (fs[t] >= TAUL){
                        unsigned e = ii[j]*4u + (unsigned)t;
                        unsigned q = e/(unsigned)CC;
                        unsigned c = e - q*(unsigned)CC;
                        float val = fsig_acc(fs[t]);
                        if (c == (unsigned)(CC-1)) val *= __ldg(&O[q]);
                        unsigned long long key =
                            ((unsigned long long)__float_as_uint(val) << 32)
                          | (unsigned)(~e);
                        unsigned p = atomicAdd(&g_cnt[b], 1u);
                        if (p < (unsigned)CAP) g_key[b][p] = key;
                    }
                }
            }
        }
    }

    // ---------------- ticket: last block of batch b becomes selector ------
    __shared__ unsigned sTicket;
    __syncthreads();
    if (tid==0){
        __threadfence();
        sTicket = atomicAdd(&g_done[b], 1u);
    }
    __syncthreads();
    if (sTicket != (unsigned)(GPB-1)) return;

    // ---------------- Phase 2: per-batch select + epilogue ----------------
    __shared__ unsigned           hist[2048];     // 8 KB
    __shared__ unsigned long long tl[TIECAP];     // 4 KB (value ties)
    __shared__ unsigned long long outk[KTOP];     // 800 B
    __shared__ unsigned           wsum[8];
    __shared__ unsigned long long wmax[8];
    __shared__ unsigned           sPref, sRemain, sNc, sTc, sCnt, sTie;
    __shared__ unsigned long long sPrev;

    // early: issue target_sizes loads so DRAM latency overlaps the barriers
    int tsOdd = 0;                // OR of odd words -> int64 iff all zero
    #pragma unroll
    for (int i2=1; i2<32; i2+=2) tsOdd |= tsraw[i2];
    int w0 = tsraw[4*b+0], w1 = tsraw[4*b+1], w2 = tsraw[4*b+2], w3 = tsraw[4*b+3];

    if (tid==0){
        sCnt = g_cnt[b];
        g_cnt[b]  = 0u;     // replay invariants
        g_done[b] = 0u;
        sPref = 0u; sRemain = KTOP; sNc = 0u; sTc = 0u; sTie = 0u;
    }
    __syncthreads();
    unsigned cnt = sCnt;
    bool bad = (cnt < (unsigned)KTOP) || (cnt > (unsigned)CAPS);
    int lane = tid & 31, wid = tid >> 5;
    const unsigned long long* GK = g_key[b];

    if (!bad){
        int n = (int)cnt;

        // one L2 round: load this thread's keys into registers
        unsigned long long kreg[KPT];
        #pragma unroll
        for (int j=0;j<KPT;j++){
            int i = tid + j*256;
            kreg[j] = (i < n) ? __ldg(&GK[i]) : 0ull;   // 0 = below everything
        }

        // ---- 3-pass radix select on the 32-bit value (11/11/10 bits) -----
        const int shf[3]  = {21, 10, 0};
        const int bits[3] = {11, 11, 10};
        #pragma unroll
        for (int p=0; p<3; p++){
            unsigned rem  = sRemain;
            unsigned pref = sPref;
            int shift = shf[p], nb = bits[p];
            #pragma unroll
            for (int j=0;j<8;j++) hist[tid + 256*j] = 0u;
            __syncthreads();
            #pragma unroll
            for (int j=0;j<KPT;j++){
                int i = tid + j*256;
                if (i < n){
                    unsigned v = (unsigned)(kreg[j] >> 32);
                    bool m = (p==0) || ((v >> (shift+nb)) == pref);
                    if (m) atomicAdd(&hist[(v>>shift) & ((1u<<nb)-1u)], 1u);
                }
            }
            __syncthreads();
            // descending scan: thread t covers bins [2047-8t .. 2040-8t]
            int base = 2047 - tid*8;
            unsigned h[8]; unsigned sum = 0;
            #pragma unroll
            for (int j=0;j<8;j++){ h[j] = hist[base-j]; sum += h[j]; }
            unsigned inc = sum;
            #pragma unroll
            for (int off=1; off<32; off<<=1){
                unsigned o = __shfl_up_sync(0xFFFFFFFFu, inc, off);
                if (lane>=off) inc += o;
            }
            if (lane==31) wsum[wid] = inc;
            __syncthreads();
            unsigned wbase = 0;
            for (int w=0; w<wid; w++) wbase += wsum[w];
            unsigned excl = wbase + (inc - sum);
            if (excl < rem && rem <= excl + sum){
                unsigned r = rem - excl;
                unsigned c = 0;
                #pragma unroll
                for (int j=0;j<8;j++){
                    if (c + h[j] >= r){
                        sPref   = (pref << nb) | (unsigned)(base - j);
                        sRemain = r - c;
                        if (p==2) sTie = h[j];
                        break;
                    }
                    c += h[j];
                }
            }
            __syncthreads();
        }
        unsigned V   = sPref;       // exact 32-bit pivot value bits
        unsigned rem = sRemain;     // how many ties to take (by smallest idx)
        unsigned tc0 = sTie;        // exact tie count from histogram

        if (tc0 <= (unsigned)TIECAP){
            // collect from registers: val > V -> outk; val == V -> tie list
            #pragma unroll
            for (int j=0;j<KPT;j++){
                int i = tid + j*256;
                if (i < n){
                    unsigned long long kk = kreg[j];
                    unsigned v = (unsigned)(kk >> 32);
                    if (v > V){
                        outk[atomicAdd(&sNc,1u)] = kk;
                    } else if (v == V){
                        unsigned p2 = atomicAdd(&sTc,1u);
                        if (p2 < (unsigned)TIECAP) tl[p2] = kk;
                    }
                }
            }
            __syncthreads();
            unsigned tc = sTc;
            // tie-break: take the rem ties with largest key (= smallest idx)
            for (unsigned j=tid; j<tc; j+=256u){
                unsigned long long kj = tl[j];
                unsigned c = 0;
                for (unsigned i=0;i<tc;i++) c += (tl[i] > kj) ? 1u : 0u;
                if (c < rem) outk[atomicAdd(&sNc,1u)] = kj;
            }
            __syncthreads();

            // rank sort of 100 unique keys
            unsigned long long myk = 0ull; int rank = 0;
            if (tid < KTOP){
                myk = outk[tid];
                for (int j=0;j<KTOP;j++) rank += (outk[j] > myk) ? 1 : 0;
            }
            __syncthreads();
            if (tid < KTOP) outk[rank] = myk;
            __syncthreads();
        } else {
            bad = true;   // absurd tie degeneracy -> exact fallback below
        }
    }

    if (bad){
        // Fully correct fallback: 100 bounded full-batch argmax passes.
        if (tid==0) sPrev = 0xFFFFFFFFFFFFFFFFull;
        __syncthreads();
        for (int k=0;k<KTOP;k++){
            unsigned long long prev = sPrev;
            unsigned long long bm = 0ull;
            for (unsigned i=tid; i<(unsigned)NPB; i+=256u){
                float lg = L[i];
                float v  = fsig_acc(lg);
                unsigned q = i/(unsigned)CC;
                unsigned c = i - q*(unsigned)CC;
                if (c == (unsigned)(CC-1)) v *= O[q];
                unsigned long long kk =
                    ((unsigned long long)__float_as_uint(v) << 32) | (unsigned)(~i);
                if (kk < prev && kk > bm) bm = kk;
            }
            #pragma unroll
            for (int off=16; off; off>>=1){
                unsigned long long om = __shfl_down_sync(0xFFFFFFFFu, bm, off);
                if (om > bm) bm = om;
            }
            if (lane==0) wmax[wid]=bm;
            __syncthreads();
            if (tid==0){
                unsigned long long best=0ull;
                for (int w=0;w<8;w++) if (wmax[w]>best) best=wmax[w];
                outk[k]=best; sPrev=best;
            }
            __syncthreads();
        }
    }

    // ---- target_sizes (loaded early): int64 iff all odd words zero -------
    bool is64 = (tsOdd == 0);
    long long t0, t1;
    if (is64){
        t0 = (long long)(unsigned)w0 | ((long long)w1 << 32);
        t1 = (long long)(unsigned)w2 | ((long long)w3 << 32);
    } else {
        t0 = (long long)tsraw[2*b]; t1 = (long long)tsraw[2*b+1];
    }
    float scale = (float)(t0 > t1 ? t0 : t1);
    float limW  = (float)t1;
    float limH  = (float)t0;
    const float4* BX = (const float4*)boxes + (size_t)b*QQ;

    for (int k=tid; k<KTOP; k+=256){
        unsigned long long kk = outk[k];
        float    score = __uint_as_float((unsigned)(kk>>32));
        unsigned idx   = ~((unsigned)(kk & 0xFFFFFFFFull));
        unsigned q   = idx/(unsigned)CC;
        unsigned lab = idx - q*(unsigned)CC;

        dout[b*KTOP + k]            = score;
        dout[BB*KTOP + b*KTOP + k]  = (float)lab;

        float4 bx = BX[q];
        float x0 = (bx.x - 0.5f*bx.z)*scale;
        float y0 = (bx.y - 0.5f*bx.w)*scale;
        float x1 = (bx.x + 0.5f*bx.z)*scale;
        float y1 = (bx.y + 0.5f*bx.w)*scale;
        x0 = fminf(fmaxf(x0,0.0f), limW);
        y0 = fminf(fmaxf(y0,0.0f), limH);
        x1 = fminf(fmaxf(x1,0.0f), limW);
        y1 = fminf(fmaxf(y1,0.0f), limH);
        float* ob = dout + 2*BB*KTOP + ((size_t)(b*KTOP + k))*4;
        ob[0]=x0; ob[1]=y0; ob[2]=x1; ob[3]=y1;
    }
}

// ---------------------------------------------------------------------------
extern "C" void kernel_launch(void* const* d_in, const int* in_sizes, int n_in,
                              void* d_out, int out_size)
{
    const float* logits = (const float*)d_in[0];
    const float* obj    = (const float*)d_in[1];
    const float* boxes  = (const float*)d_in[2];
    const int*   tsraw  = (const int*)  d_in[3];
    float* dout = (float*)d_out;

    k_fused<<<BB*GPB, 256>>>(logits, obj, boxes, tsraw, dout);   // 10848 blocks
}